// round 1
// baseline (speedup 1.0000x reference)
#include <cuda_runtime.h>

#define TT 20
#define MM 6
#define DD 9
#define NODES (TT*MM)      // 120
#define NTHREADS 128

// ---------------- FMA-only activations (no MUFU) ----------------

// e^{-a} for a >= 0 (clamped to 80). FMA/ALU pipes only.
__device__ __forceinline__ float fexpneg(float a) {
    a = fminf(a, 80.0f);
    float t = a * 1.4426950408889634f;       // a * log2(e), t in [0, ~115.4]
    float z = t + 12582912.0f;               // round-to-nearest via 1.5*2^23
    int   n = __float_as_int(z) - 0x4B400000;
    float u = (float)n - t;                  // u in [-0.5, 0.5]; want 2^{-t} = 2^{-n} * 2^{u}
    float p = 1.3333558146e-3f;
    p = fmaf(p, u, 9.6181291076e-3f);
    p = fmaf(p, u, 5.5504108664e-2f);
    p = fmaf(p, u, 2.4022650696e-1f);
    p = fmaf(p, u, 6.9314718056e-1f);
    p = fmaf(p, u, 1.0f);
    return __int_as_float((127 - n) << 23) * p;
}

// 1/y for y in [1,2], 3 Newton iterations (err ~3e-9)
__device__ __forceinline__ float recip1to2(float y) {
    float r = fmaf(-0.5f, y, 1.45710678f);
    r = r * fmaf(-y, r, 2.0f);
    r = r * fmaf(-y, r, 2.0f);
    r = r * fmaf(-y, r, 2.0f);
    return r;
}

__device__ __forceinline__ float fsigmoid(float x) {
    float e = fexpneg(fabsf(x));
    float r = recip1to2(1.0f + e);           // sigmoid(|x|)
    return (x >= 0.0f) ? r : (1.0f - r);
}

__device__ __forceinline__ float ftanh_(float x) {
    float e = fexpneg(2.0f * fabsf(x));
    float r = recip1to2(1.0f + e);
    float th = fmaf(2.0f, r, -1.0f);         // tanh(|x|)
    return (x >= 0.0f) ? th : -th;
}

// ---------------- small dot helpers (vectorized smem reads) ----------------

__device__ __forceinline__ float dot9(const float* __restrict__ w, const float* r) {
    float4 a = *(const float4*)w;
    float4 b = *(const float4*)(w + 4);
    float acc = w[8] * r[8];
    acc = fmaf(a.x, r[0], acc); acc = fmaf(a.y, r[1], acc);
    acc = fmaf(a.z, r[2], acc); acc = fmaf(a.w, r[3], acc);
    acc = fmaf(b.x, r[4], acc); acc = fmaf(b.y, r[5], acc);
    acc = fmaf(b.z, r[6], acc); acc = fmaf(b.w, r[7], acc);
    return acc;
}

__device__ __forceinline__ float dot18(const float* __restrict__ w, const float* r) {
    float acc = 0.0f;
    #pragma unroll
    for (int q = 0; q < 4; q++) {
        float4 a = *(const float4*)(w + 4*q);
        acc = fmaf(a.x, r[4*q+0], acc);
        acc = fmaf(a.y, r[4*q+1], acc);
        acc = fmaf(a.z, r[4*q+2], acc);
        acc = fmaf(a.w, r[4*q+3], acc);
    }
    acc = fmaf(w[16], r[16], acc);
    acc = fmaf(w[17], r[17], acc);
    return acc;
}

__device__ __forceinline__ void load9(float* r, const float* __restrict__ p) {
    float4 a = *(const float4*)p;
    float4 b = *(const float4*)(p + 4);
    r[0]=a.x; r[1]=a.y; r[2]=a.z; r[3]=a.w;
    r[4]=b.x; r[5]=b.y; r[6]=b.z; r[7]=b.w;
    r[8]=p[8];
}

// ---------------- fused kernel: one CTA per graph n ----------------

__global__ __launch_bounds__(NTHREADS)
void gnn_lstm_kernel(
    const float* __restrict__ nf,   const float* __restrict__ pos,  const float* __restrict__ attm,
    const float* __restrict__ msgW, const float* __restrict__ msgb,
    const float* __restrict__ gWih, const float* __restrict__ gWhh,
    const float* __restrict__ gbih, const float* __restrict__ gbhh,
    const float* __restrict__ ro1W, const float* __restrict__ ro1b,
    const float* __restrict__ ro2W, const float* __restrict__ ro2b,
    const float* __restrict__ lfWih, const float* __restrict__ lfWhh,
    const float* __restrict__ lfbih, const float* __restrict__ lfbhh,
    const float* __restrict__ lbWih, const float* __restrict__ lbWhh,
    const float* __restrict__ lbbih, const float* __restrict__ lbbhh,
    const float* __restrict__ lr1W, const float* __restrict__ lr1b,
    const float* __restrict__ lr2W, const float* __restrict__ lr2b,
    const int* __restrict__ numrec,
    float* __restrict__ out_p, float* __restrict__ out_p0)
{
    // weights, rows padded to 12 (or 20) floats for 16B-aligned LDS.128 broadcasts
    __shared__ __align__(16) float s_msgW[9*12];
    __shared__ __align__(16) float s_msgb[12];
    __shared__ __align__(16) float s_gWih[27*12];
    __shared__ __align__(16) float s_gWhh[27*12];
    __shared__ __align__(16) float s_gbih[28];
    __shared__ __align__(16) float s_gbhh[28];
    __shared__ __align__(16) float s_ro1W[9*12];
    __shared__ __align__(16) float s_ro1b[12];
    __shared__ __align__(16) float s_ro2W[7*12];
    __shared__ __align__(16) float s_ro2b[8];
    __shared__ __align__(16) float s_lWih[2][36*12];
    __shared__ __align__(16) float s_lWhh[2][36*12];
    __shared__ __align__(16) float s_lb[2][40];      // bih + bhh combined
    __shared__ __align__(16) float s_lr1W[9*20];     // rows of 18, stride 20
    __shared__ __align__(16) float s_lr1b[12];
    __shared__ __align__(16) float s_lr2W[7*12];
    __shared__ __align__(16) float s_lr2b[8];
    // data
    __shared__ __align__(16) float s_x[NODES*12];    // node features -> final hidden (stride 12)
    __shared__ __align__(16) float s_buf[NODES*20];  // GRU msg (stride 12) / LSTM out (stride 20)
    __shared__ __align__(16) float s_att[NODES*8];   // masked att rows (stride 8)
    __shared__ __align__(16) float s_hs[12*12];      // per-(m,dir) LSTM h state

    const int tid = threadIdx.x;
    const int n   = blockIdx.x;

    // ---- cooperative weight staging (pad rows) ----
    auto ldp = [&](float* dst, const float* src, int rows, int cols, int stride) {
        for (int i = tid; i < rows*cols; i += NTHREADS)
            dst[(i/cols)*stride + (i%cols)] = src[i];
    };
    ldp(s_msgW, msgW, 9, 9, 12);
    ldp(s_gWih, gWih, 27, 9, 12);
    ldp(s_gWhh, gWhh, 27, 9, 12);
    ldp(s_ro1W, ro1W, 9, 9, 12);
    ldp(s_ro2W, ro2W, 7, 9, 12);
    ldp(s_lWih[0], lfWih, 36, 9, 12);
    ldp(s_lWhh[0], lfWhh, 36, 9, 12);
    ldp(s_lWih[1], lbWih, 36, 9, 12);
    ldp(s_lWhh[1], lbWhh, 36, 9, 12);
    ldp(s_lr1W, lr1W, 9, 18, 20);
    ldp(s_lr2W, lr2W, 7, 9, 12);
    if (tid < 9)  s_msgb[tid] = msgb[tid];
    if (tid < 27) { s_gbih[tid] = gbih[tid]; s_gbhh[tid] = gbhh[tid]; }
    if (tid < 9)  s_ro1b[tid] = ro1b[tid];
    if (tid < 7)  s_ro2b[tid] = ro2b[tid];
    if (tid < 36) { s_lb[0][tid] = lfbih[tid] + lfbhh[tid];
                    s_lb[1][tid] = lbbih[tid] + lbbhh[tid]; }
    if (tid < 9)  s_lr1b[tid] = lr1b[tid];
    if (tid < 7)  s_lr2b[tid] = lr2b[tid];

    // mask depends only on num_rec[n, 0] (reference uses num_rec[:, 0:1])
    const int nr0 = numrec[(size_t)n * TT];

    // ---- stage node features (concat) + masked attention ----
    for (int i = tid; i < NODES*3; i += NTHREADS)
        s_x[(i/3)*12 + (i%3)] = nf[(size_t)n * NODES * 3 + i];
    for (int i = tid; i < NODES*6; i += NTHREADS)
        s_x[(i/6)*12 + 3 + (i%6)] = pos[(size_t)n * NODES * 6 + i];
    for (int i = tid; i < NODES*6; i += NTHREADS) {
        int c = i % 6;
        float v = attm[(size_t)n * NODES * 6 + i];
        s_att[(i/6)*8 + c] = (c < nr0) ? v : 0.0f;
    }
    __syncthreads();

    // ================= GRU message passing (thread = node (t,m)) =================
    const bool act = tid < NODES;
    const int t = tid / MM, m = tid % MM;
    float h[9];
    float attr[6];
    float vm = 0.0f;
    if (act) {
        #pragma unroll
        for (int d = 0; d < 9; d++) h[d] = s_x[tid*12 + d];
        #pragma unroll
        for (int j = 0; j < 6; j++) attr[j] = s_att[tid*8 + j];
        vm = (m < nr0) ? 1.0f : 0.0f;
    }

    #pragma unroll
    for (int rd = 0; rd < 2; rd++) {
        if (act) {
            #pragma unroll
            for (int g = 0; g < 9; g++)
                s_buf[tid*12 + g] = s_msgb[g] + dot9(s_msgW + g*12, h);
        }
        __syncthreads();
        if (act) {
            float mg[9];
            #pragma unroll
            for (int d = 0; d < 9; d++) mg[d] = 0.0f;
            #pragma unroll
            for (int j = 0; j < 6; j++) {
                const float* mp = s_buf + (t*6 + j)*12;
                float aj = attr[j];
                #pragma unroll
                for (int d = 0; d < 9; d++) mg[d] = fmaf(aj, mp[d], mg[d]);
            }
            float hn[9];
            #pragma unroll
            for (int d = 0; d < 9; d++) {
                float a0  = s_gbih[d]      + dot9(s_gWih + d*12,        mg)
                          + s_gbhh[d]      + dot9(s_gWhh + d*12,        h);
                float a1  = s_gbih[9+d]    + dot9(s_gWih + (9+d)*12,    mg)
                          + s_gbhh[9+d]    + dot9(s_gWhh + (9+d)*12,    h);
                float gx2 = s_gbih[18+d]   + dot9(s_gWih + (18+d)*12,   mg);
                float gh2 = s_gbhh[18+d]   + dot9(s_gWhh + (18+d)*12,   h);
                float r  = fsigmoid(a0);
                float z  = fsigmoid(a1);
                float nn = ftanh_(fmaf(r, gh2, gx2));
                hn[d] = fmaf(z, h[d] - nn, nn) * vm;   // ((1-z)*n + z*h) * valid
            }
            #pragma unroll
            for (int d = 0; d < 9; d++) h[d] = hn[d];
        }
        __syncthreads();
    }

    // ---- store hidden for LSTM input, readout p0 ----
    if (act) {
        #pragma unroll
        for (int d = 0; d < 9; d++) s_x[tid*12 + d] = h[d];
        float q[9];
        #pragma unroll
        for (int d = 0; d < 9; d++)
            q[d] = fmaxf(s_ro1b[d] + dot9(s_ro1W + d*12, h), 0.0f);
        size_t base = ((size_t)n * NODES + tid) * 7;
        #pragma unroll
        for (int k = 0; k < 7; k++)
            out_p0[base + k] = (s_ro2b[k] + dot9(s_ro2W + k*12, q)) * vm;
    }
    for (int i = tid; i < 144; i += NTHREADS) s_hs[i] = 0.0f;
    __syncthreads();

    // ================= Bi-LSTM (thread = (dir, m, d)) =================
    const bool lact = tid < 108;
    const int g    = lact ? (tid / 9) : 0;   // 0..11
    const int d2   = tid % 9;
    const int lm   = g % 6;
    const int dirn = g / 6;                  // 0 fwd, 1 bwd
    const float* Wi = s_lWih[dirn];
    const float* Wh = s_lWhh[dirn];
    const float* bb = s_lb[dirn];
    float c = 0.0f;

    for (int s = 0; s < TT; s++) {
        int ts = dirn ? (TT - 1 - s) : s;
        float hd = 0.0f;
        if (lact) {
            float xr[9], hr[9];
            load9(xr, s_x + (ts*6 + lm)*12);
            load9(hr, s_hs + g*12);
            float gi = bb[d2]      + dot9(Wi + (d2)*12,      xr) + dot9(Wh + (d2)*12,      hr);
            float gf = bb[9+d2]    + dot9(Wi + (9+d2)*12,    xr) + dot9(Wh + (9+d2)*12,    hr);
            float gG = bb[18+d2]   + dot9(Wi + (18+d2)*12,   xr) + dot9(Wh + (18+d2)*12,   hr);
            float go = bb[27+d2]   + dot9(Wi + (27+d2)*12,   xr) + dot9(Wh + (27+d2)*12,   hr);
            float i_ = fsigmoid(gi);
            float f_ = fsigmoid(gf);
            float gg = ftanh_(gG);
            float o_ = fsigmoid(go);
            c  = fmaf(f_, c, i_ * gg);
            hd = o_ * ftanh_(c);
        }
        __syncthreads();   // all reads of s_hs done
        if (lact) {
            s_hs[g*12 + d2] = hd;
            s_buf[(ts*6 + lm)*20 + dirn*9 + d2] = hd;
        }
        __syncthreads();   // publish for next step
    }

    // ================= final readout p (thread = node (t,m)) =================
    if (act) {
        float o18[18];
        const float* op = s_buf + tid*20;
        #pragma unroll
        for (int k = 0; k < 18; k++) o18[k] = op[k];
        float q[9];
        #pragma unroll
        for (int dd = 0; dd < 9; dd++)
            q[dd] = fmaxf(s_lr1b[dd] + dot18(s_lr1W + dd*20, o18), 0.0f);
        size_t base = ((size_t)n * NODES + tid) * 7;
        #pragma unroll
        for (int k = 0; k < 7; k++)
            out_p[base + k] = (s_lr2b[k] + dot9(s_lr2W + k*12, q)) * vm;
    }
}

extern "C" void kernel_launch(void* const* d_in, const int* in_sizes, int n_in,
                              void* d_out, int out_size)
{
    const float* nf    = (const float*)d_in[0];
    const float* pos   = (const float*)d_in[1];
    const float* attm  = (const float*)d_in[2];
    const float* msgW  = (const float*)d_in[3];
    const float* msgb  = (const float*)d_in[4];
    const float* gWih  = (const float*)d_in[5];
    const float* gWhh  = (const float*)d_in[6];
    const float* gbih  = (const float*)d_in[7];
    const float* gbhh  = (const float*)d_in[8];
    const float* ro1W  = (const float*)d_in[9];
    const float* ro1b  = (const float*)d_in[10];
    const float* ro2W  = (const float*)d_in[11];
    const float* ro2b  = (const float*)d_in[12];
    const float* lfWih = (const float*)d_in[13];
    const float* lfWhh = (const float*)d_in[14];
    const float* lfbih = (const float*)d_in[15];
    const float* lfbhh = (const float*)d_in[16];
    const float* lbWih = (const float*)d_in[17];
    const float* lbWhh = (const float*)d_in[18];
    const float* lbbih = (const float*)d_in[19];
    const float* lbbhh = (const float*)d_in[20];
    const float* lr1W  = (const float*)d_in[21];
    const float* lr1b  = (const float*)d_in[22];
    const float* lr2W  = (const float*)d_in[23];
    const float* lr2b  = (const float*)d_in[24];
    const int*   nrec  = (const int*)d_in[25];

    int N = in_sizes[25] / TT;
    float* out = (float*)d_out;
    size_t half = (size_t)N * TT * MM * 7;   // pred_label first, pred_label0 second

    gnn_lstm_kernel<<<N, NTHREADS>>>(
        nf, pos, attm, msgW, msgb, gWih, gWhh, gbih, gbhh,
        ro1W, ro1b, ro2W, ro2b,
        lfWih, lfWhh, lfbih, lfbhh, lbWih, lbWhh, lbbih, lbbhh,
        lr1W, lr1b, lr2W, lr2b, nrec,
        out, out + half);
}